// round 2
// baseline (speedup 1.0000x reference)
#include <cuda_runtime.h>

#define CCH 64          // C_in == C_out == 64
#define TM  128         // pairs per block tile
#define BN_EPS 1e-5f

// channel stats scratch: [0..63] = sum, [64..127] = sum of squares
__device__ float g_stats[2 * CCH];

// ---------------- packed f32x2 helpers (Blackwell FFMA2 path) ----------------
__device__ __forceinline__ unsigned long long ffma2(unsigned long long a,
                                                    unsigned long long b,
                                                    unsigned long long c) {
    unsigned long long d;
    asm("fma.rn.f32x2 %0, %1, %2, %3;" : "=l"(d) : "l"(a), "l"(b), "l"(c));
    return d;
}
__device__ __forceinline__ unsigned long long bcast2(float x) {
    unsigned long long d;
    asm("mov.b64 %0, {%1, %1};" : "=l"(d) : "f"(x));
    return d;
}
__device__ __forceinline__ unsigned long long pack2(float x, float y) {
    unsigned long long d;
    asm("mov.b64 %0, {%1, %2};" : "=l"(d) : "f"(x), "f"(y));
    return d;
}
__device__ __forceinline__ float2 unpack2(unsigned long long v) {
    float2 r;
    asm("mov.b64 {%0, %1}, %2;" : "=f"(r.x), "=f"(r.y) : "l"(v));
    return r;
}
// vectorized global reduction: 4 consecutive floats in one L2 atomic op
__device__ __forceinline__ void red_add_v4(float* p, float a, float b, float c, float d) {
    asm volatile("red.global.add.v4.f32 [%0], {%1, %2, %3, %4};"
                 :: "l"(p), "f"(a), "f"(b), "f"(c), "f"(d) : "memory");
}

// ---------------------------------------------------------------------------
__global__ void k_zero_stats() {
    if (threadIdx.x < 2 * CCH) g_stats[threadIdx.x] = 0.0f;
}

// ---------------------------------------------------------------------------
// Per-offset GEMM with gather (A rows) and scatter-add (C rows).
// Block = 256 threads, tile = TM pairs x 64 out-channels, K = 64.
__global__ void __launch_bounds__(256, 1)
k_scatter(const float* __restrict__ feat, const float* __restrict__ W,
          const int* __restrict__ pin, const int* __restrict__ pout,
          float* __restrict__ out, int P, int blocksPerK)
{
    __shared__ float As[CCH][TM + 4];   // [k][m] transposed: conflict-free LDS.128
    __shared__ float Bs[CCH][CCH + 4];  // [k][n] == weight[k] layout

    const int tid = threadIdx.x;
    const int k  = blockIdx.x / blocksPerK;
    const int pb = blockIdx.x - k * blocksPerK;
    const int pairBase = pb * TM;
    const int* pin_k  = pin  + (size_t)k * P;
    const int* pout_k = pout + (size_t)k * P;

    // ---- load weight tile: 64x64 f32 (already [c_in][c_out] row-major) ----
    {
        const float4* Wv = (const float4*)(W + (size_t)k * CCH * CCH);
        #pragma unroll
        for (int t = tid; t < CCH * CCH / 4; t += 256) {
            int kk = t >> 4, n4 = t & 15;
            float4 w = Wv[t];
            *(float4*)&Bs[kk][n4 * 4] = w;
        }
    }

    // ---- gather A: TM rows x 64 ch, stored transposed As[kk][m] ----
    // lanes 0..15 take consecutive m -> conflict-free STS (lower/upper 16 banks)
    {
        const int mloc = tid & 15;
        const int kb   = tid >> 4;   // 0..15, chunk of 4 channels
        #pragma unroll
        for (int it = 0; it < TM / 16; ++it) {
            int m  = it * 16 + mloc;
            int gp = pairBase + m;
            int idx = (gp < P) ? pin_k[gp] : 0;
            float4 f = *(const float4*)(feat + (size_t)idx * CCH + kb * 4);
            As[kb * 4 + 0][m] = f.x;
            As[kb * 4 + 1][m] = f.y;
            As[kb * 4 + 2][m] = f.z;
            As[kb * 4 + 3][m] = f.w;
        }
    }
    __syncthreads();

    // ---- register microtile: 4 rows (m) x 8 cols (n) as 16 f32x2 accs ----
    const int ty = tid >> 3;       // 0..31
    const int tx = tid & 7;        // 0..7
    const int m0 = ty * 4;
    const int n0 = tx * 8;

    unsigned long long acc[4][4];
    #pragma unroll
    for (int i = 0; i < 4; ++i)
        #pragma unroll
        for (int j = 0; j < 4; ++j) acc[i][j] = 0ull;

    #pragma unroll 16
    for (int kk = 0; kk < CCH; ++kk) {
        float4 a  = *(const float4*)&As[kk][m0];
        float4 b0 = *(const float4*)&Bs[kk][n0];
        float4 b1 = *(const float4*)&Bs[kk][n0 + 4];
        unsigned long long bb0 = pack2(b0.x, b0.y);
        unsigned long long bb1 = pack2(b0.z, b0.w);
        unsigned long long bb2 = pack2(b1.x, b1.y);
        unsigned long long bb3 = pack2(b1.z, b1.w);
        float av[4] = {a.x, a.y, a.z, a.w};
        #pragma unroll
        for (int i = 0; i < 4; ++i) {
            unsigned long long ai = bcast2(av[i]);
            acc[i][0] = ffma2(ai, bb0, acc[i][0]);
            acc[i][1] = ffma2(ai, bb1, acc[i][1]);
            acc[i][2] = ffma2(ai, bb2, acc[i][2]);
            acc[i][3] = ffma2(ai, bb3, acc[i][3]);
        }
    }

    // ---- scatter-add epilogue: 2x red.global.add.v4.f32 per row ----
    #pragma unroll
    for (int i = 0; i < 4; ++i) {
        int gp = pairBase + m0 + i;
        if (gp < P) {
            int o = pout_k[gp];
            float* dst = out + (size_t)o * CCH + n0;
            float2 v0 = unpack2(acc[i][0]);
            float2 v1 = unpack2(acc[i][1]);
            float2 v2 = unpack2(acc[i][2]);
            float2 v3 = unpack2(acc[i][3]);
            red_add_v4(dst,     v0.x, v0.y, v1.x, v1.y);
            red_add_v4(dst + 4, v2.x, v2.y, v3.x, v3.y);
        }
    }
}

// ---------------------------------------------------------------------------
// Channel-wise sum / sum-of-squares over the accumulated (pre-bias) output.
__global__ void __launch_bounds__(256)
k_stats(const float* __restrict__ out, int N)
{
    __shared__ float sh[256], sh2[256];
    const int tid = threadIdx.x;
    const int c = tid & 63;
    float s = 0.0f, s2 = 0.0f;
    for (int r = blockIdx.x * 4 + (tid >> 6); r < N; r += gridDim.x * 4) {
        float v = out[(size_t)r * CCH + c];
        s  += v;
        s2 += v * v;
    }
    sh[tid] = s; sh2[tid] = s2;
    __syncthreads();
    if (tid < 64) {
        s  = sh[tid]  + sh[tid + 64]  + sh[tid + 128]  + sh[tid + 192];
        s2 = sh2[tid] + sh2[tid + 64] + sh2[tid + 128] + sh2[tid + 192];
        atomicAdd(&g_stats[tid], s);
        atomicAdd(&g_stats[64 + tid], s2);
    }
}

// ---------------------------------------------------------------------------
// Fused BN (training-mode batch stats) + ReLU, in place, float4-vectorized.
// Note: conv bias cancels exactly through BN (mean shifts by the same constant),
// so it never needs to be added.
__global__ void __launch_bounds__(256)
k_norm(float* __restrict__ out, const float* __restrict__ gamma,
       const float* __restrict__ beta, int N)
{
    float4* o4 = (float4*)out;
    const int total4 = N * (CCH / 4);
    int i = blockIdx.x * blockDim.x + threadIdx.x;
    const int stride = gridDim.x * blockDim.x;   // multiple of 16 -> fixed channels
    if (i >= total4) return;

    const int cb = (i & 15) * 4;                 // base channel of this thread's vec4
    const float ninv = 1.0f / (float)N;
    float mean[4], scale[4], shift[4];
    #pragma unroll
    for (int j = 0; j < 4; ++j) {
        int c = cb + j;
        float m = g_stats[c] * ninv;
        float var = fmaxf(g_stats[64 + c] * ninv - m * m, 0.0f);
        mean[j]  = m;
        scale[j] = rsqrtf(var + BN_EPS) * gamma[c];
        shift[j] = beta[c];
    }
    for (; i < total4; i += stride) {
        float4 v = o4[i];
        v.x = fmaxf((v.x - mean[0]) * scale[0] + shift[0], 0.0f);
        v.y = fmaxf((v.y - mean[1]) * scale[1] + shift[1], 0.0f);
        v.z = fmaxf((v.z - mean[2]) * scale[2] + shift[2], 0.0f);
        v.w = fmaxf((v.w - mean[3]) * scale[3] + shift[3], 0.0f);
        o4[i] = v;
    }
}

// ---------------------------------------------------------------------------
extern "C" void kernel_launch(void* const* d_in, const int* in_sizes, int n_in,
                              void* d_out, int out_size)
{
    const float* feat  = (const float*)d_in[0];   // [N_in, 64]
    const float* W     = (const float*)d_in[1];   // [K3, 64, 64]
    // d_in[2] = bias (cancels through BN), d_in[3] = gamma, d_in[4] = beta
    const float* gamma = (const float*)d_in[3];
    const float* beta  = (const float*)d_in[4];
    const int* pin  = (const int*)d_in[5];        // [K3, P]
    const int* pout = (const int*)d_in[6];        // [K3, P]

    const int K3 = in_sizes[1] / (CCH * CCH);
    const int P  = in_sizes[5] / K3;
    const int Nout = out_size / CCH;

    float* out = (float*)d_out;

    cudaMemsetAsync(d_out, 0, (size_t)out_size * sizeof(float), 0);
    k_zero_stats<<<1, 128>>>();

    const int blocksPerK = (P + TM - 1) / TM;
    k_scatter<<<K3 * blocksPerK, 256>>>(feat, W, pin, pout, out, P, blocksPerK);

    int statsBlocks = (Nout + 3) / 4;
    if (statsBlocks > 1184) statsBlocks = 1184;
    k_stats<<<statsBlocks, 256>>>(out, Nout);

    int total4 = Nout * (CCH / 4);
    int normBlocks = (total4 + 255) / 256;
    if (normBlocks > 4096) normBlocks = 4096;
    k_norm<<<normBlocks, 256>>>(out, gamma, beta, Nout);
}

// round 14
// speedup vs baseline: 1.6493x; 1.6493x over previous
#include <cuda_runtime.h>
#include <cstdint>

#define CCH   64        // C_in == C_out == 64
#define TMR   256       // pairs (M rows) per CTA tile
#define BN_EPS 1e-5f

// smem layout (floats): As[64][APAD] then Bs[64][BPAD]
#define APAD 260        // 256 + 4 : keeps float4 alignment (260*4 % 16 == 0)
#define BPAD 68
#define SMEM_FLOATS (CCH * APAD + CCH * BPAD)
#define SMEM_BYTES  (SMEM_FLOATS * 4)   // 83,968 B -> 2 CTAs/SM

__device__ float g_stats[2 * CCH];   // [0..63]=sum, [64..127]=sum of squares

// ---------------- packed f32x2 helpers (Blackwell FFMA2 path) ----------------
typedef unsigned long long ull;
static __device__ __forceinline__ ull ffma2(ull a, ull b, ull c) {
    ull d;
    asm("fma.rn.f32x2 %0, %1, %2, %3;" : "=l"(d) : "l"(a), "l"(b), "l"(c));
    return d;
}
static __device__ __forceinline__ ull bcast2(float x) {
    ull d; asm("mov.b64 %0, {%1, %1};" : "=l"(d) : "f"(x)); return d;
}
static __device__ __forceinline__ ull pack2(float x, float y) {
    ull d; asm("mov.b64 %0, {%1, %2};" : "=l"(d) : "f"(x), "f"(y)); return d;
}
static __device__ __forceinline__ float2 unpack2(ull v) {
    float2 r; asm("mov.b64 {%0, %1}, %2;" : "=f"(r.x), "=f"(r.y) : "l"(v)); return r;
}
static __device__ __forceinline__ void red4(float* p, float a, float b, float c, float d) {
    asm volatile("red.global.add.v4.f32 [%0], {%1,%2,%3,%4};"
                 :: "l"(p), "f"(a), "f"(b), "f"(c), "f"(d) : "memory");
}

// ===========================================================================
// Gather -> 256x64x64 GEMM (16m x 8n register microtile, f32x2 FMA) -> scatter
// ===========================================================================
__global__ void __launch_bounds__(128, 2)
k_scatter(const float* __restrict__ feat, const float* __restrict__ W,
          const int* __restrict__ pin, const int* __restrict__ pout,
          float* __restrict__ out, int P, int tilesPerK)
{
    extern __shared__ float smem[];
    float* As = smem;                 // [64][APAD], transposed: As[kk][m]
    float* Bs = smem + CCH * APAD;    // [64][BPAD], Bs[kk][n]

    const int tid = threadIdx.x;
    const int k   = blockIdx.x / tilesPerK;
    const int pb  = blockIdx.x - k * tilesPerK;
    const int base = pb * TMR;
    const int* pin_k  = pin  + (size_t)k * P;
    const int* pout_k = pout + (size_t)k * P;

    // ---- weight tile: 64x64 f32, W[k] is [c_in][c_out] row-major = Bs[kk][n] ----
    {
        const float4* Wv = (const float4*)(W + (size_t)k * CCH * CCH);
        #pragma unroll
        for (int t = tid; t < CCH * CCH / 4; t += 128) {
            float4 w = Wv[t];
            int kk = t >> 4, n4 = (t & 15) * 4;
            *(float4*)&Bs[kk * BPAD + n4] = w;
        }
    }

    // ---- gather A: 2 rows per thread, stored transposed As[kk][m] ----
    #pragma unroll
    for (int rr = 0; rr < 2; ++rr) {
        const int m  = tid + rr * 128;
        const int gp = base + m;
        const int idx = (gp < P) ? __ldg(pin_k + gp) : 0;
        const float4* src = (const float4*)(feat + (size_t)idx * CCH);
        #pragma unroll
        for (int j = 0; j < 16; ++j) {
            float4 v = __ldg(src + j);
            As[(j * 4 + 0) * APAD + m] = v.x;
            As[(j * 4 + 1) * APAD + m] = v.y;
            As[(j * 4 + 2) * APAD + m] = v.z;
            As[(j * 4 + 3) * APAD + m] = v.w;
        }
    }
    __syncthreads();

    // ---- 16m x 8n register microtile: 64 f32x2 accumulators ----
    const int ty = tid >> 3;          // 0..15
    const int tx = tid & 7;           // 0..7
    const int m0 = ty * 16;
    const int n0 = tx * 8;

    ull acc[16][4];
    #pragma unroll
    for (int i = 0; i < 16; ++i)
        #pragma unroll
        for (int j = 0; j < 4; ++j) acc[i][j] = 0ull;

    const float* Ab = As + m0;
    const float* Bb = Bs + n0;

    #pragma unroll 4
    for (int kk = 0; kk < CCH; ++kk) {
        float4 a0 = *(const float4*)(Ab + kk * APAD + 0);
        float4 a1 = *(const float4*)(Ab + kk * APAD + 4);
        float4 a2 = *(const float4*)(Ab + kk * APAD + 8);
        float4 a3 = *(const float4*)(Ab + kk * APAD + 12);
        float4 b0 = *(const float4*)(Bb + kk * BPAD);
        float4 b1 = *(const float4*)(Bb + kk * BPAD + 4);
        ull bb0 = pack2(b0.x, b0.y), bb1 = pack2(b0.z, b0.w);
        ull bb2 = pack2(b1.x, b1.y), bb3 = pack2(b1.z, b1.w);
        float av[16] = {a0.x, a0.y, a0.z, a0.w, a1.x, a1.y, a1.z, a1.w,
                        a2.x, a2.y, a2.z, a2.w, a3.x, a3.y, a3.z, a3.w};
        #pragma unroll
        for (int i = 0; i < 16; ++i) {
            ull ai = bcast2(av[i]);
            acc[i][0] = ffma2(ai, bb0, acc[i][0]);
            acc[i][1] = ffma2(ai, bb1, acc[i][1]);
            acc[i][2] = ffma2(ai, bb2, acc[i][2]);
            acc[i][3] = ffma2(ai, bb3, acc[i][3]);
        }
    }

    // ---- scatter-add epilogue: 2x red.global.add.v4.f32 per owned row ----
    #pragma unroll
    for (int i = 0; i < 16; ++i) {
        const int gp = base + m0 + i;
        if (gp < P) {
            const int o = __ldg(pout_k + gp);
            float* dst = out + (size_t)o * CCH + n0;
            float2 v0 = unpack2(acc[i][0]);
            float2 v1 = unpack2(acc[i][1]);
            float2 v2 = unpack2(acc[i][2]);
            float2 v3 = unpack2(acc[i][3]);
            red4(dst,     v0.x, v0.y, v1.x, v1.y);
            red4(dst + 4, v2.x, v2.y, v3.x, v3.y);
        }
    }
}

// ---------------------------------------------------------------------------
__global__ void __launch_bounds__(256)
k_zero(float4* __restrict__ out4, int n4)
{
    int i = blockIdx.x * blockDim.x + threadIdx.x;
    const int s = gridDim.x * blockDim.x;
    const float4 z = make_float4(0.f, 0.f, 0.f, 0.f);
    for (; i < n4; i += s) out4[i] = z;
    if (blockIdx.x == 0 && threadIdx.x < 2 * CCH) g_stats[threadIdx.x] = 0.0f;
}

// ---------------------------------------------------------------------------
__global__ void __launch_bounds__(256)
k_stats(const float* __restrict__ out, int N)
{
    __shared__ float sh[256], sh2[256];
    const int tid = threadIdx.x;
    const int c = tid & 63;
    float s = 0.0f, s2 = 0.0f;
    for (int r = blockIdx.x * 4 + (tid >> 6); r < N; r += gridDim.x * 4) {
        float v = out[(size_t)r * CCH + c];
        s += v; s2 += v * v;
    }
    sh[tid] = s; sh2[tid] = s2;
    __syncthreads();
    if (tid < 64) {
        s  = sh[tid]  + sh[tid + 64]  + sh[tid + 128]  + sh[tid + 192];
        s2 = sh2[tid] + sh2[tid + 64] + sh2[tid + 128] + sh2[tid + 192];
        atomicAdd(&g_stats[tid], s);
        atomicAdd(&g_stats[64 + tid], s2);
    }
}

// ---------------------------------------------------------------------------
// Fused BN (batch stats; conv bias cancels exactly through training-mode BN)
// + ReLU, in place, float4-vectorized.
__global__ void __launch_bounds__(256)
k_norm(float* __restrict__ out, const float* __restrict__ gamma,
       const float* __restrict__ beta, int N)
{
    float4* o4 = (float4*)out;
    const int total4 = N * (CCH / 4);
    int i = blockIdx.x * blockDim.x + threadIdx.x;
    const int stride = gridDim.x * blockDim.x;   // multiple of 16 -> fixed channels
    if (i >= total4) return;

    const int cb = (i & 15) * 4;
    const float ninv = 1.0f / (float)N;
    float mean[4], scale[4], shift[4];
    #pragma unroll
    for (int j = 0; j < 4; ++j) {
        int c = cb + j;
        float m = g_stats[c] * ninv;
        float var = fmaxf(g_stats[64 + c] * ninv - m * m, 0.0f);
        mean[j] = m;
        scale[j] = rsqrtf(var + BN_EPS) * gamma[c];
        shift[j] = beta[c];
    }
    for (; i < total4; i += stride) {
        float4 v = o4[i];
        v.x = fmaxf((v.x - mean[0]) * scale[0] + shift[0], 0.0f);
        v.y = fmaxf((v.y - mean[1]) * scale[1] + shift[1], 0.0f);
        v.z = fmaxf((v.z - mean[2]) * scale[2] + shift[2], 0.0f);
        v.w = fmaxf((v.w - mean[3]) * scale[3] + shift[3], 0.0f);
        o4[i] = v;
    }
}

// ---------------------------------------------------------------------------
extern "C" void kernel_launch(void* const* d_in, const int* in_sizes, int n_in,
                              void* d_out, int out_size)
{
    const float* feat  = (const float*)d_in[0];   // [N_in, 64]
    const float* W     = (const float*)d_in[1];   // [K3, 64, 64]
    // d_in[2] = bias (cancels through training-mode BN)
    const float* gamma = (const float*)d_in[3];
    const float* beta  = (const float*)d_in[4];
    const int* pin  = (const int*)d_in[5];        // [K3, P]
    const int* pout = (const int*)d_in[6];        // [K3, P]

    const int K3 = in_sizes[1] / (CCH * CCH);
    const int P  = in_sizes[5] / K3;
    const int Nout = out_size / CCH;
    float* out = (float*)d_out;

    const int tilesPerK = (P + TMR - 1) / TMR;

    static int smem_set = 0;
    if (!smem_set) {
        cudaFuncSetAttribute(k_scatter, cudaFuncAttributeMaxDynamicSharedMemorySize, SMEM_BYTES);
        smem_set = 1;
    }

    // 4 launches per call: (1) zero+stats-clear, (2) scatter-GEMM, (3) stats, (4) norm
    k_zero<<<1184, 256>>>((float4*)out, Nout * (CCH / 4));

    k_scatter<<<K3 * tilesPerK, 128, SMEM_BYTES>>>(feat, W, pin, pout, out, P, tilesPerK);

    int statsBlocks = (Nout + 3) / 4;
    if (statsBlocks > 1184) statsBlocks = 1184;
    k_stats<<<statsBlocks, 256>>>(out, Nout);

    int total4 = Nout * (CCH / 4);
    int normBlocks = (total4 + 255) / 256;
    if (normBlocks > 4096) normBlocks = 4096;
    k_norm<<<normBlocks, 256>>>(out, gamma, beta, Nout);
}

// round 15
// speedup vs baseline: 1.9103x; 1.1582x over previous
#include <cuda_runtime.h>
#include <cuda_bf16.h>
#include <cstdint>

#define CCH 64          // C_in == C_out == 64
#define MT  128         // pairs (M rows) per CTA tile
#define APITCH 72       // bf16 elems per smem row (144 B) -> ldmatrix conflict-free
#define BN_EPS 1e-5f

// smem byte offsets (dynamic smem, 1024-aligned base)
#define OFF_AHI 0
#define OFF_ALO (MT * APITCH * 2)                 // 18432
#define OFF_BHI (2 * MT * APITCH * 2)             // 36864
#define OFF_BLO (OFF_BHI + CCH * APITCH * 2)      // 46080
#define SMEM_BYTES (OFF_BLO + CCH * APITCH * 2)   // 55296 -> 2 CTAs/SM

__device__ float g_stats[2 * CCH];   // [0..63]=sum, [64..127]=sum of squares

// ======================= PTX helpers =======================
static __device__ __forceinline__ uint32_t smem_u32(const void* p) {
    uint32_t a;
    asm("{ .reg .u64 t; cvta.to.shared.u64 t, %1; cvt.u32.u64 %0, t; }" : "=r"(a) : "l"(p));
    return a;
}
static __device__ __forceinline__ void ldsm_x4(uint32_t& r0, uint32_t& r1,
                                               uint32_t& r2, uint32_t& r3, uint32_t addr) {
    asm volatile("ldmatrix.sync.aligned.m8n8.x4.shared.b16 {%0,%1,%2,%3}, [%4];"
                 : "=r"(r0), "=r"(r1), "=r"(r2), "=r"(r3) : "r"(addr));
}
static __device__ __forceinline__ void ldsm_x4_t(uint32_t& r0, uint32_t& r1,
                                                 uint32_t& r2, uint32_t& r3, uint32_t addr) {
    asm volatile("ldmatrix.sync.aligned.m8n8.x4.trans.shared.b16 {%0,%1,%2,%3}, [%4];"
                 : "=r"(r0), "=r"(r1), "=r"(r2), "=r"(r3) : "r"(addr));
}
static __device__ __forceinline__ void mma_bf16(float* c, const uint32_t* a,
                                                uint32_t b0, uint32_t b1) {
    asm volatile(
        "mma.sync.aligned.m16n8k16.row.col.f32.bf16.bf16.f32 "
        "{%0,%1,%2,%3}, {%4,%5,%6,%7}, {%8,%9}, {%0,%1,%2,%3};"
        : "+f"(c[0]), "+f"(c[1]), "+f"(c[2]), "+f"(c[3])
        : "r"(a[0]), "r"(a[1]), "r"(a[2]), "r"(a[3]), "r"(b0), "r"(b1));
}
static __device__ __forceinline__ void red2(float* p, float a, float b) {
    asm volatile("red.global.add.v2.f32 [%0], {%1,%2};" :: "l"(p), "f"(a), "f"(b) : "memory");
}
static __device__ __forceinline__ void sts2(uint32_t addr, uint32_t a, uint32_t b) {
    asm volatile("st.shared.v2.b32 [%0], {%1,%2};" :: "r"(addr), "r"(a), "r"(b));
}
// split f32 pair -> bf16x2 hi + bf16x2 lo (packed u32 each)
static __device__ __forceinline__ void split2(float x, float y, uint32_t& hi, uint32_t& lo) {
    __nv_bfloat162 h = __float22bfloat162_rn(make_float2(x, y));
    float2 hf = __bfloat1622float2(h);
    __nv_bfloat162 l = __float22bfloat162_rn(make_float2(x - hf.x, y - hf.y));
    hi = *reinterpret_cast<uint32_t*>(&h);
    lo = *reinterpret_cast<uint32_t*>(&l);
}

// ===========================================================================
// Gather -> 128x64x64 GEMM via mma.sync bf16 (2-word split, 3 passes) -> scatter
// ===========================================================================
__global__ void __launch_bounds__(256, 2)
k_scatter(const float* __restrict__ feat, const float* __restrict__ W,
          const int* __restrict__ pin, const int* __restrict__ pout,
          float* __restrict__ out, int P, int tilesPerK)
{
    extern __shared__ __align__(1024) char smem[];
    const uint32_t sb = smem_u32(smem);

    const int tid  = threadIdx.x;
    const int warp = tid >> 5;
    const int lane = tid & 31;
    const int k    = blockIdx.x / tilesPerK;
    const int pb   = blockIdx.x - k * tilesPerK;
    const int base = pb * MT;
    const int* pin_k  = pin  + (size_t)k * P;
    const int* pout_k = pout + (size_t)k * P;

    // ---- weight tile: W[k] is [ci][co] row-major = B[k=ci][n=co]; hi/lo bf16 ----
    {
        const float4* Wv = (const float4*)(W + (size_t)k * CCH * CCH);
        #pragma unroll
        for (int t = tid; t < CCH * CCH / 4; t += 256) {
            const int kk = t >> 4, n4 = (t & 15) * 4;
            float4 v = __ldg(Wv + t);
            uint32_t h01, l01, h23, l23;
            split2(v.x, v.y, h01, l01);
            split2(v.z, v.w, h23, l23);
            const uint32_t off = (uint32_t)(kk * APITCH + n4) * 2;
            sts2(sb + OFF_BHI + off, h01, h23);
            sts2(sb + OFF_BLO + off, l01, l23);
        }
    }

    // ---- gather A: 2 threads per row, 8 float4 each; hi/lo bf16 split ----
    {
        const int row = tid >> 1;
        const int j0  = (tid & 1) * 8;
        int gp = base + row;
        if (gp >= P) gp = P - 1;
        const int idx = __ldg(pin_k + gp);
        const float4* src = (const float4*)(feat + (size_t)idx * CCH) + j0;
        #pragma unroll
        for (int j = 0; j < 8; ++j) {
            float4 v = __ldg(src + j);
            uint32_t h01, l01, h23, l23;
            split2(v.x, v.y, h01, l01);
            split2(v.z, v.w, h23, l23);
            const uint32_t off = (uint32_t)(row * APITCH + (j0 + j) * 4) * 2;
            sts2(sb + OFF_AHI + off, h01, h23);
            sts2(sb + OFF_ALO + off, l01, l23);
        }
    }
    __syncthreads();

    // ---- 3-pass MMA: Ahi*Bhi + Ahi*Blo + Alo*Bhi, f32 accumulate ----
    float c[8][4];
    #pragma unroll
    for (int i = 0; i < 8; ++i)
        #pragma unroll
        for (int j = 0; j < 4; ++j) c[i][j] = 0.0f;

    const int warpM = warp * 16;
    const int lrow  = lane & 15;
    const int lhalf = (lane >> 4) * 8;
    // lane-invariant parts of ldmatrix addresses
    const uint32_t aLaneOff = (uint32_t)((warpM + lrow) * APITCH + lhalf) * 2;
    const uint32_t bLaneOff = (uint32_t)(lrow * APITCH + lhalf) * 2;

    #pragma unroll
    for (int pass = 0; pass < 3; ++pass) {
        const uint32_t aBase = sb + ((pass == 2) ? OFF_ALO : OFF_AHI) + aLaneOff;
        const uint32_t bBase = sb + ((pass == 1) ? OFF_BLO : OFF_BHI) + bLaneOff;
        #pragma unroll
        for (int ks = 0; ks < 4; ++ks) {
            uint32_t a[4];
            ldsm_x4(a[0], a[1], a[2], a[3], aBase + (uint32_t)(ks * 16) * 2);
            #pragma unroll
            for (int nb4 = 0; nb4 < 4; ++nb4) {
                uint32_t b0, b1, b2, b3;
                ldsm_x4_t(b0, b1, b2, b3,
                          bBase + (uint32_t)(ks * 16 * APITCH + nb4 * 16) * 2);
                mma_bf16(c[nb4 * 2],     a, b0, b1);
                mma_bf16(c[nb4 * 2 + 1], a, b2, b3);
            }
        }
    }

    // ---- scatter-add epilogue: red.global.add.v2.f32 per (row, n-block) ----
    const int groupID = lane >> 2;
    const int tig     = lane & 3;
    const int gp0 = base + warpM + groupID;
    const int gp1 = gp0 + 8;
    const bool v0 = (gp0 < P), v1 = (gp1 < P);
    const int o0 = v0 ? __ldg(pout_k + gp0) : 0;
    const int o1 = v1 ? __ldg(pout_k + gp1) : 0;
    float* d0 = out + (size_t)o0 * CCH + 2 * tig;
    float* d1 = out + (size_t)o1 * CCH + 2 * tig;
    #pragma unroll
    for (int nb = 0; nb < 8; ++nb) {
        if (v0) red2(d0 + nb * 8, c[nb][0], c[nb][1]);
        if (v1) red2(d1 + nb * 8, c[nb][2], c[nb][3]);
    }
}

// ---------------------------------------------------------------------------
__global__ void __launch_bounds__(256)
k_zero(float4* __restrict__ out4, int n4)
{
    int i = blockIdx.x * blockDim.x + threadIdx.x;
    const int s = gridDim.x * blockDim.x;
    const float4 z = make_float4(0.f, 0.f, 0.f, 0.f);
    for (; i < n4; i += s) out4[i] = z;
    if (blockIdx.x == 0 && threadIdx.x < 2 * CCH) g_stats[threadIdx.x] = 0.0f;
}

// ---------------------------------------------------------------------------
__global__ void __launch_bounds__(256)
k_stats(const float* __restrict__ out, int N)
{
    __shared__ float sh[256], sh2[256];
    const int tid = threadIdx.x;
    const int c = tid & 63;
    float s = 0.0f, s2 = 0.0f;
    for (int r = blockIdx.x * 4 + (tid >> 6); r < N; r += gridDim.x * 4) {
        float v = out[(size_t)r * CCH + c];
        s += v; s2 += v * v;
    }
    sh[tid] = s; sh2[tid] = s2;
    __syncthreads();
    if (tid < 64) {
        s  = sh[tid]  + sh[tid + 64]  + sh[tid + 128]  + sh[tid + 192];
        s2 = sh2[tid] + sh2[tid + 64] + sh2[tid + 128] + sh2[tid + 192];
        atomicAdd(&g_stats[tid], s);
        atomicAdd(&g_stats[64 + tid], s2);
    }
}

// ---------------------------------------------------------------------------
// Fused BN (batch stats; conv bias cancels exactly through training-mode BN)
// + ReLU, in place, float4-vectorized.
__global__ void __launch_bounds__(256)
k_norm(float* __restrict__ out, const float* __restrict__ gamma,
       const float* __restrict__ beta, int N)
{
    float4* o4 = (float4*)out;
    const int total4 = N * (CCH / 4);
    int i = blockIdx.x * blockDim.x + threadIdx.x;
    const int stride = gridDim.x * blockDim.x;   // multiple of 16 -> fixed channels
    if (i >= total4) return;

    const int cb = (i & 15) * 4;
    const float ninv = 1.0f / (float)N;
    float mean[4], scale[4], shift[4];
    #pragma unroll
    for (int j = 0; j < 4; ++j) {
        int c = cb + j;
        float m = g_stats[c] * ninv;
        float var = fmaxf(g_stats[64 + c] * ninv - m * m, 0.0f);
        mean[j] = m;
        scale[j] = rsqrtf(var + BN_EPS) * gamma[c];
        shift[j] = beta[c];
    }
    for (; i < total4; i += stride) {
        float4 v = o4[i];
        v.x = fmaxf((v.x - mean[0]) * scale[0] + shift[0], 0.0f);
        v.y = fmaxf((v.y - mean[1]) * scale[1] + shift[1], 0.0f);
        v.z = fmaxf((v.z - mean[2]) * scale[2] + shift[2], 0.0f);
        v.w = fmaxf((v.w - mean[3]) * scale[3] + shift[3], 0.0f);
        o4[i] = v;
    }
}

// ---------------------------------------------------------------------------
extern "C" void kernel_launch(void* const* d_in, const int* in_sizes, int n_in,
                              void* d_out, int out_size)
{
    const float* feat  = (const float*)d_in[0];   // [N_in, 64]
    const float* W     = (const float*)d_in[1];   // [K3, 64, 64]
    // d_in[2] = bias (cancels through training-mode BN)
    const float* gamma = (const float*)d_in[3];
    const float* beta  = (const float*)d_in[4];
    const int* pin  = (const int*)d_in[5];        // [K3, P]
    const int* pout = (const int*)d_in[6];        // [K3, P]

    const int K3 = in_sizes[1] / (CCH * CCH);
    const int P  = in_sizes[5] / K3;
    const int Nout = out_size / CCH;
    float* out = (float*)d_out;

    const int tilesPerK = (P + MT - 1) / MT;

    static int smem_set = 0;
    if (!smem_set) {
        cudaFuncSetAttribute(k_scatter, cudaFuncAttributeMaxDynamicSharedMemorySize, SMEM_BYTES);
        smem_set = 1;
    }

    // 4 launches per call: (1) zero+stats-clear, (2) scatter-GEMM, (3) stats, (4) norm
    k_zero<<<1184, 256>>>((float4*)out, Nout * (CCH / 4));

    k_scatter<<<K3 * tilesPerK, 256, SMEM_BYTES>>>(feat, W, pin, pout, out, P, tilesPerK);

    int statsBlocks = (Nout + 3) / 4;
    if (statsBlocks > 1184) statsBlocks = 1184;
    k_stats<<<statsBlocks, 256>>>(out, Nout);

    int total4 = Nout * (CCH / 4);
    int normBlocks = (total4 + 255) / 256;
    if (normBlocks > 4096) normBlocks = 4096;
    k_norm<<<normBlocks, 256>>>(out, gamma, beta, Nout);
}